// round 7
// baseline (speedup 1.0000x reference)
#include <cuda_runtime.h>

// Batched 512-point complex forward DFT (== reference complex matmul by
// W[h,j] = exp(-2*pi*i*j*h/512)), computed as a radix-8^3 FFT.
//
// R6: persistent loop (ITER=4 row-groups per block) with software prefetch of
// the next iteration's inputs overlapping the current iteration's smem/barrier
// phases. Loop-invariant twiddle bases hoisted. Streaming ld/st hints.

#define NROWS 32768
#define FPB 4              // FFTs per iteration per block
#define ITER 4             // row-groups per block
#define TPF 64             // threads per FFT
#define BLOCK (FPB * TPF)  // 256
#define BUFSZ 576          // stage1 stride 72 * 8
#define S2 66              // stage-2 store stride (2 mod 16 -> conflict-free)

__device__ __forceinline__ float2 cadd(float2 a, float2 b) { return make_float2(a.x + b.x, a.y + b.y); }
__device__ __forceinline__ float2 csub(float2 a, float2 b) { return make_float2(a.x - b.x, a.y - b.y); }
__device__ __forceinline__ float2 cmul(float2 a, float2 b) {
    return make_float2(fmaf(a.x, b.x, -a.y * b.y), fmaf(a.x, b.y, a.y * b.x));
}
__device__ __forceinline__ float2 mul_mi(float2 a) { return make_float2(a.y, -a.x); }  // *(-i)

// 8-point DFT: A[k] = sum_j a[j] * W8^(jk),  W8 = exp(-2*pi*i/8)
__device__ __forceinline__ void dft8(const float2* a, float2* A) {
    float2 e0p = cadd(a[0], a[4]), e0m = csub(a[0], a[4]);
    float2 e1p = cadd(a[2], a[6]), e1m = csub(a[2], a[6]);
    float2 E0 = cadd(e0p, e1p), E2 = csub(e0p, e1p);
    float2 mie = mul_mi(e1m);
    float2 E1 = cadd(e0m, mie);
    float2 E3 = csub(e0m, mie);

    float2 o0p = cadd(a[1], a[5]), o0m = csub(a[1], a[5]);
    float2 o1p = cadd(a[3], a[7]), o1m = csub(a[3], a[7]);
    float2 O0 = cadd(o0p, o1p), O2 = csub(o0p, o1p);
    float2 mio = mul_mi(o1m);
    float2 O1 = cadd(o0m, mio);
    float2 O3 = csub(o0m, mio);

    const float c = 0.70710678118654752440f;  // sqrt(2)/2
    float2 t0 = O0;
    float2 t1 = make_float2(c * (O1.x + O1.y), c * (O1.y - O1.x));   // (c,-c)*O1
    float2 t2 = mul_mi(O2);                                          // (0,-1)*O2
    float2 t3 = make_float2(c * (O3.y - O3.x), -c * (O3.x + O3.y));  // (-c,-c)*O3

    A[0] = cadd(E0, t0); A[4] = csub(E0, t0);
    A[1] = cadd(E1, t1); A[5] = csub(E1, t1);
    A[2] = cadd(E2, t2); A[6] = csub(E2, t2);
    A[3] = cadd(E3, t3); A[7] = csub(E3, t3);
}

__global__ __launch_bounds__(BLOCK, 4)
void fft512_kernel(const float* __restrict__ xre, const float* __restrict__ xim,
                   const float* __restrict__ wre, const float* __restrict__ wim,
                   float* __restrict__ out) {
    __shared__ float2 tw2[512];           // W512^a exact base twiddles
    __shared__ float2 tws2[64];           // tws2[i] = W512^(8*(i&7))
    __shared__ float2 buf[FPB][BUFSZ];    // exchange buffer

    const int tid = threadIdx.x;
    const int f = tid >> 6;       // FFT slot (0..3)
    const int t = tid & 63;       // thread within FFT
    const int h0s = t >> 3;       // stage-2 digit h0
    const int j1a = t & 7;        // stage-2 digit j1a

    // Exact twiddles from w table row 1: W^a = (w_re[512+a], w_im[512+a])
    #pragma unroll
    for (int i = tid; i < 512; i += BLOCK)
        tw2[i] = make_float2(wre[512 + i], wim[512 + i]);
    if (tid < 64)
        tws2[tid] = make_float2(wre[512 + 8 * (tid & 7)], wim[512 + 8 * (tid & 7)]);

    float2 p[8], a[8], A[8];

    // Prefetch iteration 0 inputs (16 LDG.32 in flight during twiddle sync)
    {
        const size_t row = (size_t)(blockIdx.x * ITER) * FPB + f;
        const float* xr = xre + row * 512;
        const float* xi = xim + row * 512;
        #pragma unroll
        for (int j2 = 0; j2 < 8; j2++)
            p[j2] = make_float2(__ldcs(xr + t + 64 * j2), __ldcs(xi + t + 64 * j2));
    }

    __syncthreads();  // twiddles ready

    // Loop-invariant twiddle bases
    const float2 wb1 = tw2[t];      // W512^t      (conflict-free LDS.64)
    const float2 wb2 = tws2[t];     // W512^(8*j1a)

    #pragma unroll
    for (int it = 0; it < ITER; it++) {
        const size_t row = (size_t)(blockIdx.x * ITER + it) * FPB + f;

        // ---- Stage 1: DFT8 over j2 -> digit h0; consumes p ----
        dft8(p, A);

        // Prefetch next iteration's inputs: these LDGs fly during the
        // smem/barrier phases below.
        if (it + 1 < ITER) {
            const size_t nrow = row + FPB;
            const float* xr = xre + nrow * 512;
            const float* xi = xim + nrow * 512;
            #pragma unroll
            for (int j2 = 0; j2 < 8; j2++)
                p[j2] = make_float2(__ldcs(xr + t + 64 * j2), __ldcs(xi + t + 64 * j2));
        }

        // twiddle W512^(t*h0) via chained powers of wb1
        {
            float2 w = wb1;
            #pragma unroll
            for (int h0 = 1; h0 < 8; h0++) {
                A[h0] = cmul(A[h0], w);
                if (h0 < 7) w = cmul(w, wb1);
            }
        }
        #pragma unroll
        for (int h0 = 0; h0 < 8; h0++)
            buf[f][h0 * 72 + t] = A[h0];
        __syncthreads();

        // ---- Stage 2: thread (h0s, j1a); DFT8 over j1b -> h10;
        //      twiddle W512^(8*j1a*h10); store [j1a*66 + 8*h10 + h0] ----
        #pragma unroll
        for (int j1b = 0; j1b < 8; j1b++)
            a[j1b] = buf[f][h0s * 72 + j1a + 8 * j1b];
        __syncthreads();  // reads done before buffer reuse

        dft8(a, A);
        {
            float2 w = wb2;
            #pragma unroll
            for (int h10 = 1; h10 < 8; h10++) {
                A[h10] = cmul(A[h10], w);
                if (h10 < 7) w = cmul(w, wb2);
            }
        }
        #pragma unroll
        for (int h10 = 0; h10 < 8; h10++)
            buf[f][j1a * S2 + 8 * h10 + h0s] = A[h10];
        __syncthreads();

        // ---- Stage 3: thread t owns (h0 = t&7, h10 = t>>3); stage-2 layout
        //      index 8*h10 + h0 == t -> consecutive loads ----
        #pragma unroll
        for (int j = 0; j < 8; j++)
            a[j] = buf[f][j * S2 + t];
        __syncthreads();  // buf free for next iteration's stage-1 stores

        dft8(a, A);

        // h = t + 64*h11: 256B contiguous per warp per store
        float2* o2 = reinterpret_cast<float2*>(out) + row * 512;
        #pragma unroll
        for (int h11 = 0; h11 < 8; h11++)
            __stcs(o2 + t + 64 * h11, A[h11]);
    }
}

extern "C" void kernel_launch(void* const* d_in, const int* in_sizes, int n_in,
                              void* d_out, int out_size) {
    const float* x_re = (const float*)d_in[0];
    const float* x_im = (const float*)d_in[1];
    const float* w_re = (const float*)d_in[2];
    const float* w_im = (const float*)d_in[3];
    float* out = (float*)d_out;

    dim3 grid(NROWS / (FPB * ITER));  // 2048 blocks
    dim3 block(BLOCK);                // 256 threads
    fft512_kernel<<<grid, block>>>(x_re, x_im, w_re, w_im, out);
}

// round 8
// speedup vs baseline: 1.0816x; 1.0816x over previous
#include <cuda_runtime.h>

// Batched 512-point complex forward DFT (== reference complex matmul by
// W[h,j] = exp(-2*pi*i*j*h/512)), computed as a radix-8^3 FFT.
//
// R7: back to the R4 operating point (regs<=32, full occupancy), plus:
//  - twiddle smem removed entirely (each thread loads only its 2 base
//    twiddles W^t and W^(8*(t&7)) straight from the w table, L2-resident)
//  - FPB=2 / 128-thread blocks / 16 CTAs per SM: narrower barriers, 16
//    independent phase-offset blocks per SM keep DRAM+L1 fed.

#define NROWS 32768
#define FPB 2              // FFTs per block
#define TPF 64             // threads per FFT
#define BLOCK (FPB * TPF)  // 128
#define BUFSZ 576          // stage1 stride 72 * 8
#define S2 66              // stage-2 store stride (2 mod 16 -> conflict-free)

__device__ __forceinline__ float2 cadd(float2 a, float2 b) { return make_float2(a.x + b.x, a.y + b.y); }
__device__ __forceinline__ float2 csub(float2 a, float2 b) { return make_float2(a.x - b.x, a.y - b.y); }
__device__ __forceinline__ float2 cmul(float2 a, float2 b) {
    return make_float2(fmaf(a.x, b.x, -a.y * b.y), fmaf(a.x, b.y, a.y * b.x));
}
__device__ __forceinline__ float2 mul_mi(float2 a) { return make_float2(a.y, -a.x); }  // *(-i)

// 8-point DFT: A[k] = sum_j a[j] * W8^(jk),  W8 = exp(-2*pi*i/8)
__device__ __forceinline__ void dft8(const float2* a, float2* A) {
    float2 e0p = cadd(a[0], a[4]), e0m = csub(a[0], a[4]);
    float2 e1p = cadd(a[2], a[6]), e1m = csub(a[2], a[6]);
    float2 E0 = cadd(e0p, e1p), E2 = csub(e0p, e1p);
    float2 mie = mul_mi(e1m);
    float2 E1 = cadd(e0m, mie);
    float2 E3 = csub(e0m, mie);

    float2 o0p = cadd(a[1], a[5]), o0m = csub(a[1], a[5]);
    float2 o1p = cadd(a[3], a[7]), o1m = csub(a[3], a[7]);
    float2 O0 = cadd(o0p, o1p), O2 = csub(o0p, o1p);
    float2 mio = mul_mi(o1m);
    float2 O1 = cadd(o0m, mio);
    float2 O3 = csub(o0m, mio);

    const float c = 0.70710678118654752440f;  // sqrt(2)/2
    float2 t0 = O0;
    float2 t1 = make_float2(c * (O1.x + O1.y), c * (O1.y - O1.x));   // (c,-c)*O1
    float2 t2 = mul_mi(O2);                                          // (0,-1)*O2
    float2 t3 = make_float2(c * (O3.y - O3.x), -c * (O3.x + O3.y));  // (-c,-c)*O3

    A[0] = cadd(E0, t0); A[4] = csub(E0, t0);
    A[1] = cadd(E1, t1); A[5] = csub(E1, t1);
    A[2] = cadd(E2, t2); A[6] = csub(E2, t2);
    A[3] = cadd(E3, t3); A[7] = csub(E3, t3);
}

__global__ __launch_bounds__(BLOCK, 16)
void fft512_kernel(const float* __restrict__ xre, const float* __restrict__ xim,
                   const float* __restrict__ wre, const float* __restrict__ wim,
                   float* __restrict__ out) {
    __shared__ float2 buf[FPB][BUFSZ];    // exchange buffer (9.2 KB)

    const int tid = threadIdx.x;
    const int f = tid >> 6;       // FFT slot (0..1)
    const int t = tid & 63;       // thread within FFT
    const int h0s = t >> 3;       // stage-2 digit h0
    const int j1a = t & 7;        // stage-2 digit j1a
    const size_t row = (size_t)blockIdx.x * FPB + f;

    // Per-thread exact base twiddles from w table row 1 (L2-resident):
    //   wb1 = W512^t, wb2 = W512^(8*j1a)
    const float2 wb1 = make_float2(wre[512 + t], wim[512 + t]);
    const float2 wb2 = make_float2(wre[512 + 8 * j1a], wim[512 + 8 * j1a]);

    const float* xr = xre + row * 512;
    const float* xi = xim + row * 512;

    float2 a[8], A[8];
    // Stage 1 input: a[j2] = x[t + 64*j2]   (coalesced 128B/warp per j2)
    #pragma unroll
    for (int j2 = 0; j2 < 8; j2++)
        a[j2] = make_float2(__ldcs(xr + t + 64 * j2), __ldcs(xi + t + 64 * j2));

    // ---- Stage 1: DFT8 over j2 -> digit h0; twiddle W512^(t*h0); [h0*72+t] ----
    dft8(a, A);
    {
        float2 w = wb1;
        #pragma unroll
        for (int h0 = 1; h0 < 8; h0++) {
            A[h0] = cmul(A[h0], w);
            if (h0 < 7) w = cmul(w, wb1);
        }
    }
    #pragma unroll
    for (int h0 = 0; h0 < 8; h0++)
        buf[f][h0 * 72 + t] = A[h0];
    __syncthreads();

    // ---- Stage 2: thread (h0s, j1a); DFT8 over j1b -> h10;
    //      twiddle W512^(8*j1a*h10); store [j1a*66 + 8*h10 + h0] ----
    #pragma unroll
    for (int j1b = 0; j1b < 8; j1b++)
        a[j1b] = buf[f][h0s * 72 + j1a + 8 * j1b];
    __syncthreads();  // reads done before buffer reuse

    dft8(a, A);
    {
        float2 w = wb2;
        #pragma unroll
        for (int h10 = 1; h10 < 8; h10++) {
            A[h10] = cmul(A[h10], w);
            if (h10 < 7) w = cmul(w, wb2);
        }
    }
    #pragma unroll
    for (int h10 = 0; h10 < 8; h10++)
        buf[f][j1a * S2 + 8 * h10 + h0s] = A[h10];
    __syncthreads();

    // ---- Stage 3: thread t owns (h0 = t&7, h10 = t>>3); stage-2 layout index
    //      8*h10 + h0 == t -> consecutive loads, fully coalesced stores ----
    #pragma unroll
    for (int j = 0; j < 8; j++)
        a[j] = buf[f][j * S2 + t];

    dft8(a, A);

    // h = t + 64*h11: 256B contiguous per warp per store
    float2* o2 = reinterpret_cast<float2*>(out) + row * 512;
    #pragma unroll
    for (int h11 = 0; h11 < 8; h11++)
        __stcs(o2 + t + 64 * h11, A[h11]);
}

extern "C" void kernel_launch(void* const* d_in, const int* in_sizes, int n_in,
                              void* d_out, int out_size) {
    const float* x_re = (const float*)d_in[0];
    const float* x_im = (const float*)d_in[1];
    const float* w_re = (const float*)d_in[2];
    const float* w_im = (const float*)d_in[3];
    float* out = (float*)d_out;

    dim3 grid(NROWS / FPB);   // 16384 blocks
    dim3 block(BLOCK);        // 128 threads = 2 FFTs
    fft512_kernel<<<grid, block>>>(x_re, x_im, w_re, w_im, out);
}

// round 9
// speedup vs baseline: 1.0900x; 1.0077x over previous
#include <cuda_runtime.h>

// Batched 512-point complex forward DFT (== reference complex matmul by
// W[h,j] = exp(-2*pi*i*j*h/512)), computed as a radix-8^3 FFT.
//
// R8: FPB=1 — one FFT per 64-thread CTA, 32 CTAs/SM (occupancy cap).
// Barriers span just 2 warps; 32 independent phase-offset CTAs per SM keep
// the DRAM pipe fed through each CTA's barrier stalls. Layouts, twiddle
// scheme, and streaming hints unchanged from R7 (the proven operating point).

#define NROWS 32768
#define TPF 64             // threads per FFT == block size
#define BLOCK TPF
#define BUFSZ 576          // stage1 stride 72 * 8
#define S2 66              // stage-2 store stride (2 mod 16 -> conflict-free)

__device__ __forceinline__ float2 cadd(float2 a, float2 b) { return make_float2(a.x + b.x, a.y + b.y); }
__device__ __forceinline__ float2 csub(float2 a, float2 b) { return make_float2(a.x - b.x, a.y - b.y); }
__device__ __forceinline__ float2 cmul(float2 a, float2 b) {
    return make_float2(fmaf(a.x, b.x, -a.y * b.y), fmaf(a.x, b.y, a.y * b.x));
}
__device__ __forceinline__ float2 mul_mi(float2 a) { return make_float2(a.y, -a.x); }  // *(-i)

// 8-point DFT: A[k] = sum_j a[j] * W8^(jk),  W8 = exp(-2*pi*i/8)
__device__ __forceinline__ void dft8(const float2* a, float2* A) {
    float2 e0p = cadd(a[0], a[4]), e0m = csub(a[0], a[4]);
    float2 e1p = cadd(a[2], a[6]), e1m = csub(a[2], a[6]);
    float2 E0 = cadd(e0p, e1p), E2 = csub(e0p, e1p);
    float2 mie = mul_mi(e1m);
    float2 E1 = cadd(e0m, mie);
    float2 E3 = csub(e0m, mie);

    float2 o0p = cadd(a[1], a[5]), o0m = csub(a[1], a[5]);
    float2 o1p = cadd(a[3], a[7]), o1m = csub(a[3], a[7]);
    float2 O0 = cadd(o0p, o1p), O2 = csub(o0p, o1p);
    float2 mio = mul_mi(o1m);
    float2 O1 = cadd(o0m, mio);
    float2 O3 = csub(o0m, mio);

    const float c = 0.70710678118654752440f;  // sqrt(2)/2
    float2 t0 = O0;
    float2 t1 = make_float2(c * (O1.x + O1.y), c * (O1.y - O1.x));   // (c,-c)*O1
    float2 t2 = mul_mi(O2);                                          // (0,-1)*O2
    float2 t3 = make_float2(c * (O3.y - O3.x), -c * (O3.x + O3.y));  // (-c,-c)*O3

    A[0] = cadd(E0, t0); A[4] = csub(E0, t0);
    A[1] = cadd(E1, t1); A[5] = csub(E1, t1);
    A[2] = cadd(E2, t2); A[6] = csub(E2, t2);
    A[3] = cadd(E3, t3); A[7] = csub(E3, t3);
}

__global__ __launch_bounds__(BLOCK, 32)
void fft512_kernel(const float* __restrict__ xre, const float* __restrict__ xim,
                   const float* __restrict__ wre, const float* __restrict__ wim,
                   float* __restrict__ out) {
    __shared__ float2 buf[BUFSZ];    // exchange buffer (4.6 KB)

    const int t = threadIdx.x;    // thread within FFT (0..63)
    const int h0s = t >> 3;       // stage-2 digit h0
    const int j1a = t & 7;        // stage-2 digit j1a
    const size_t row = (size_t)blockIdx.x;

    // Per-thread exact base twiddles from w table row 1 (L2-resident):
    //   wb1 = W512^t, wb2 = W512^(8*j1a)
    const float2 wb1 = make_float2(wre[512 + t], wim[512 + t]);
    const float2 wb2 = make_float2(wre[512 + 8 * j1a], wim[512 + 8 * j1a]);

    const float* xr = xre + row * 512;
    const float* xi = xim + row * 512;

    float2 a[8], A[8];
    // Stage 1 input: a[j2] = x[t + 64*j2]   (coalesced 128B/warp per j2)
    #pragma unroll
    for (int j2 = 0; j2 < 8; j2++)
        a[j2] = make_float2(__ldcs(xr + t + 64 * j2), __ldcs(xi + t + 64 * j2));

    // ---- Stage 1: DFT8 over j2 -> digit h0; twiddle W512^(t*h0); [h0*72+t] ----
    dft8(a, A);
    {
        float2 w = wb1;
        #pragma unroll
        for (int h0 = 1; h0 < 8; h0++) {
            A[h0] = cmul(A[h0], w);
            if (h0 < 7) w = cmul(w, wb1);
        }
    }
    #pragma unroll
    for (int h0 = 0; h0 < 8; h0++)
        buf[h0 * 72 + t] = A[h0];
    __syncthreads();

    // ---- Stage 2: thread (h0s, j1a); DFT8 over j1b -> h10;
    //      twiddle W512^(8*j1a*h10); store [j1a*66 + 8*h10 + h0] ----
    #pragma unroll
    for (int j1b = 0; j1b < 8; j1b++)
        a[j1b] = buf[h0s * 72 + j1a + 8 * j1b];
    __syncthreads();  // reads done before buffer reuse

    dft8(a, A);
    {
        float2 w = wb2;
        #pragma unroll
        for (int h10 = 1; h10 < 8; h10++) {
            A[h10] = cmul(A[h10], w);
            if (h10 < 7) w = cmul(w, wb2);
        }
    }
    #pragma unroll
    for (int h10 = 0; h10 < 8; h10++)
        buf[j1a * S2 + 8 * h10 + h0s] = A[h10];
    __syncthreads();

    // ---- Stage 3: thread t owns (h0 = t&7, h10 = t>>3); stage-2 layout index
    //      8*h10 + h0 == t -> consecutive loads, fully coalesced stores ----
    #pragma unroll
    for (int j = 0; j < 8; j++)
        a[j] = buf[j * S2 + t];

    dft8(a, A);

    // h = t + 64*h11: 256B contiguous per warp per store
    float2* o2 = reinterpret_cast<float2*>(out) + row * 512;
    #pragma unroll
    for (int h11 = 0; h11 < 8; h11++)
        __stcs(o2 + t + 64 * h11, A[h11]);
}

extern "C" void kernel_launch(void* const* d_in, const int* in_sizes, int n_in,
                              void* d_out, int out_size) {
    const float* x_re = (const float*)d_in[0];
    const float* x_im = (const float*)d_in[1];
    const float* w_re = (const float*)d_in[2];
    const float* w_im = (const float*)d_in[3];
    float* out = (float*)d_out;

    dim3 grid(NROWS);     // 32768 blocks, one FFT each
    dim3 block(BLOCK);    // 64 threads
    fft512_kernel<<<grid, block>>>(x_re, x_im, w_re, w_im, out);
}

// round 10
// speedup vs baseline: 1.0992x; 1.0085x over previous
#include <cuda_runtime.h>

// Batched 512-point complex forward DFT (== reference complex matmul by
// W[h,j] = exp(-2*pi*i*j*h/512)), computed as a radix-8^3 FFT.
//
// R9 (on top of R8's FPB=1 / 64-thread / 32-CTA operating point):
//  - log-depth twiddle power trees (dep chain 6 -> 3) in both stages
//  - stage-1 exchange layout stride-10 float2 (80B/row): STS.128 x4 stores,
//    bank-conflict-free on both the 128-bit stores and the stage-2 64-bit loads
//  - launch_bounds(64,28) to give the tree registers room without spills

#define NROWS 32768
#define TPF 64             // threads per FFT == block size
#define BLOCK TPF
#define BUF1 640           // stage-1 buffer: [j1*10 + h0], j1<64 -> 640 float2
#define S2 66              // stage-2 store stride (2 mod 16 -> conflict-free)

__device__ __forceinline__ float2 cadd(float2 a, float2 b) { return make_float2(a.x + b.x, a.y + b.y); }
__device__ __forceinline__ float2 csub(float2 a, float2 b) { return make_float2(a.x - b.x, a.y - b.y); }
__device__ __forceinline__ float2 cmul(float2 a, float2 b) {
    return make_float2(fmaf(a.x, b.x, -a.y * b.y), fmaf(a.x, b.y, a.y * b.x));
}
__device__ __forceinline__ float2 mul_mi(float2 a) { return make_float2(a.y, -a.x); }  // *(-i)

// 8-point DFT: A[k] = sum_j a[j] * W8^(jk),  W8 = exp(-2*pi*i/8)
__device__ __forceinline__ void dft8(const float2* a, float2* A) {
    float2 e0p = cadd(a[0], a[4]), e0m = csub(a[0], a[4]);
    float2 e1p = cadd(a[2], a[6]), e1m = csub(a[2], a[6]);
    float2 E0 = cadd(e0p, e1p), E2 = csub(e0p, e1p);
    float2 mie = mul_mi(e1m);
    float2 E1 = cadd(e0m, mie);
    float2 E3 = csub(e0m, mie);

    float2 o0p = cadd(a[1], a[5]), o0m = csub(a[1], a[5]);
    float2 o1p = cadd(a[3], a[7]), o1m = csub(a[3], a[7]);
    float2 O0 = cadd(o0p, o1p), O2 = csub(o0p, o1p);
    float2 mio = mul_mi(o1m);
    float2 O1 = cadd(o0m, mio);
    float2 O3 = csub(o0m, mio);

    const float c = 0.70710678118654752440f;  // sqrt(2)/2
    float2 t0 = O0;
    float2 t1 = make_float2(c * (O1.x + O1.y), c * (O1.y - O1.x));   // (c,-c)*O1
    float2 t2 = mul_mi(O2);                                          // (0,-1)*O2
    float2 t3 = make_float2(c * (O3.y - O3.x), -c * (O3.x + O3.y));  // (-c,-c)*O3

    A[0] = cadd(E0, t0); A[4] = csub(E0, t0);
    A[1] = cadd(E1, t1); A[5] = csub(E1, t1);
    A[2] = cadd(E2, t2); A[6] = csub(E2, t2);
    A[3] = cadd(E3, t3); A[7] = csub(E3, t3);
}

// Apply A[h] *= wb^h for h=1..7 with a depth-3 power tree.
__device__ __forceinline__ void apply_twiddles(float2* A, float2 wb) {
    float2 w2 = cmul(wb, wb);
    A[1] = cmul(A[1], wb);
    float2 w3 = cmul(w2, wb);
    float2 w4 = cmul(w2, w2);
    A[2] = cmul(A[2], w2);
    A[3] = cmul(A[3], w3);
    A[4] = cmul(A[4], w4);
    float2 w5 = cmul(w4, wb);
    float2 w6 = cmul(w4, w2);
    float2 w7 = cmul(w4, w3);
    A[5] = cmul(A[5], w5);
    A[6] = cmul(A[6], w6);
    A[7] = cmul(A[7], w7);
}

__global__ __launch_bounds__(BLOCK, 28)
void fft512_kernel(const float* __restrict__ xre, const float* __restrict__ xim,
                   const float* __restrict__ wre, const float* __restrict__ wim,
                   float* __restrict__ out) {
    __shared__ __align__(16) float2 buf[BUF1];   // 5.1 KB exchange buffer

    const int t = threadIdx.x;    // thread within FFT (0..63)
    const int h0s = t >> 3;       // stage-2 digit h0
    const int j1a = t & 7;        // stage-2 digit j1a
    const size_t row = (size_t)blockIdx.x;

    // Per-thread exact base twiddles from w table row 1 (L2-resident):
    //   wb1 = W512^t, wb2 = W512^(8*j1a)
    const float2 wb1 = make_float2(wre[512 + t], wim[512 + t]);
    const float2 wb2 = make_float2(wre[512 + 8 * j1a], wim[512 + 8 * j1a]);

    const float* xr = xre + row * 512;
    const float* xi = xim + row * 512;

    float2 a[8], A[8];
    // Stage 1 input: a[j2] = x[t + 64*j2]   (coalesced 128B/warp per j2)
    #pragma unroll
    for (int j2 = 0; j2 < 8; j2++)
        a[j2] = make_float2(__ldcs(xr + t + 64 * j2), __ldcs(xi + t + 64 * j2));

    // ---- Stage 1: DFT8 over j2 -> digit h0; twiddle W512^(t*h0);
    //      layout [t*10 + h0] (float2 units), stored as 4x STS.128 ----
    dft8(a, A);
    apply_twiddles(A, wb1);
    {
        float4* b4 = reinterpret_cast<float4*>(buf);
        #pragma unroll
        for (int h0 = 0; h0 < 8; h0 += 2)
            b4[(10 * t + h0) >> 1] =
                make_float4(A[h0].x, A[h0].y, A[h0 + 1].x, A[h0 + 1].y);
    }
    __syncthreads();

    // ---- Stage 2: thread (h0s, j1a); DFT8 over j1b -> h10;
    //      read [ (j1a + 8*j1b)*10 + h0s ]; twiddle W512^(8*j1a*h10);
    //      store [j1a*66 + 8*h10 + h0s] ----
    #pragma unroll
    for (int j1b = 0; j1b < 8; j1b++)
        a[j1b] = buf[(j1a + 8 * j1b) * 10 + h0s];
    __syncthreads();  // reads done before buffer reuse

    dft8(a, A);
    apply_twiddles(A, wb2);
    #pragma unroll
    for (int h10 = 0; h10 < 8; h10++)
        buf[j1a * S2 + 8 * h10 + h0s] = A[h10];
    __syncthreads();

    // ---- Stage 3: thread t owns (h0 = t&7, h10 = t>>3); stage-2 layout index
    //      8*h10 + h0 == t -> consecutive loads, fully coalesced stores ----
    #pragma unroll
    for (int j = 0; j < 8; j++)
        a[j] = buf[j * S2 + t];

    dft8(a, A);

    // h = t + 64*h11: 256B contiguous per warp per store
    float2* o2 = reinterpret_cast<float2*>(out) + row * 512;
    #pragma unroll
    for (int h11 = 0; h11 < 8; h11++)
        __stcs(o2 + t + 64 * h11, A[h11]);
}

extern "C" void kernel_launch(void* const* d_in, const int* in_sizes, int n_in,
                              void* d_out, int out_size) {
    const float* x_re = (const float*)d_in[0];
    const float* x_im = (const float*)d_in[1];
    const float* w_re = (const float*)d_in[2];
    const float* w_im = (const float*)d_in[3];
    float* out = (float*)d_out;

    dim3 grid(NROWS);     // 32768 blocks, one FFT each
    dim3 block(BLOCK);    // 64 threads
    fft512_kernel<<<grid, block>>>(x_re, x_im, w_re, w_im, out);
}